// round 11
// baseline (speedup 1.0000x reference)
#include <cuda_runtime.h>
#include <cstddef>

#define NN 13
#define DD 16
#define EPB 16
#define NTHREADS 128
#define NLAYERS 4
#define NCH 4
#define BN_EPS 1e-5f
#define ADJF (NCH * NN * NN)   /* 676 floats per element */

typedef unsigned long long u64;

__device__ __forceinline__ u64 pk2(float lo, float hi) {
  u64 r; asm("mov.b64 %0, {%1, %2};" : "=l"(r) : "f"(lo), "f"(hi)); return r;
}
__device__ __forceinline__ u64 bc2(float v) { return pk2(v, v); }
__device__ __forceinline__ u64 fma2(u64 a, u64 b, u64 c) {
  u64 r; asm("fma.rn.f32x2 %0, %1, %2, %3;" : "=l"(r) : "l"(a), "l"(b), "l"(c)); return r;
}
__device__ __forceinline__ u64 mul2(u64 a, u64 b) {
  u64 r; asm("mul.rn.f32x2 %0, %1, %2;" : "=l"(r) : "l"(a), "l"(b)); return r;
}
__device__ __forceinline__ u64 add2(u64 a, u64 b) {
  u64 r; asm("add.rn.f32x2 %0, %1, %2;" : "=l"(r) : "l"(a), "l"(b)); return r;
}
__device__ __forceinline__ float hsum2(u64 v) {
  float lo, hi; asm("mov.b64 {%0, %1}, %2;" : "=f"(lo), "=f"(hi) : "l"(v));
  return lo + hi;
}
__device__ __forceinline__ float leaky(float v) { return fmaxf(v, 0.01f * v); }

struct __align__(16) Smem {
  float adj[EPB][NCH][NN][NN];   // identity layout; reused as recon staging
  float x[EPB][NN][DD];          // node features (reused for decoder temp)
  float w0[NLAYERS][DD][DD];  float b0[NLAYERS][DD];
  float w1[NLAYERS][DD][DD];  float b1[NLAYERS][DD];
  float fc1[DD][DD]; float fc1b[DD];
  float fc2[DD][DD]; float fc2b[DD];
  float dec[NCH][DD][DD]; float decb[NCH][DD];
  float wi[NN][DD];
  float bnia[NLAYERS][NN]; float bnib[NLAYERS][NN];
  float bnoa[NLAYERS][NN]; float bnob[NLAYERS][NN];
  float epsp[NLAYERS];
};

// one weight-row load (4x LDS.128 broadcast) feeding TWO packed dot products
__device__ __forceinline__ void dot16x2(const u64* a, const u64* b,
                                        const float* row, float& ra, float& rb) {
  const ulonglong2* w = reinterpret_cast<const ulonglong2*>(row);
  ulonglong2 wa = w[0], wb = w[1], wc = w[2], wd = w[3];
  u64 pa = mul2(a[0], wa.x); pa = fma2(a[1], wa.y, pa);
  pa = fma2(a[2], wb.x, pa); pa = fma2(a[3], wb.y, pa);
  u64 qa = mul2(a[4], wc.x); qa = fma2(a[5], wc.y, qa);
  qa = fma2(a[6], wd.x, qa); qa = fma2(a[7], wd.y, qa);
  ra = hsum2(add2(pa, qa));
  u64 pb = mul2(b[0], wa.x); pb = fma2(b[1], wa.y, pb);
  pb = fma2(b[2], wb.x, pb); pb = fma2(b[3], wb.y, pb);
  u64 qb = mul2(b[4], wc.x); qb = fma2(b[5], wc.y, qb);
  qb = fma2(b[6], wd.x, qb); qb = fma2(b[7], wd.y, qb);
  rb = hsum2(add2(pb, qb));
}

extern "C" __global__ void __launch_bounds__(NTHREADS, 3)
vae_kernel(const float* __restrict__ g_adj, const float* __restrict__ g_wi,
           const float* __restrict__ g_eps,
           const float* __restrict__ g_w0, const float* __restrict__ g_b0,
           const float* __restrict__ g_w1, const float* __restrict__ g_b1,
           const float* __restrict__ g_big, const float* __restrict__ g_bib,
           const float* __restrict__ g_bim, const float* __restrict__ g_biv,
           const float* __restrict__ g_bog, const float* __restrict__ g_bob,
           const float* __restrict__ g_bom, const float* __restrict__ g_bov,
           const float* __restrict__ g_fc1w, const float* __restrict__ g_fc1b,
           const float* __restrict__ g_fc2w, const float* __restrict__ g_fc2b,
           const float* __restrict__ g_decw, const float* __restrict__ g_decb,
           float* __restrict__ o_recon, float* __restrict__ o_mu,
           float* __restrict__ o_lv, int Btot)
{
  extern __shared__ unsigned char smem_raw[];
  Smem& s = *reinterpret_cast<Smem*>(smem_raw);
  const int tid = threadIdx.x;

  const int b0blk = blockIdx.x * EPB;
  const int nelem = (Btot - b0blk) < EPB ? (Btot - b0blk) : EPB;

  // ---- stage adjacency (coalesced float4, identity layout) ----
  {
    const float4* src = reinterpret_cast<const float4*>(g_adj + (size_t)b0blk * ADJF);
    float4* dst = reinterpret_cast<float4*>(&s.adj[0][0][0][0]);
    const int cnt = nelem * ADJF / 4;
    for (int i = tid; i < cnt; i += NTHREADS) dst[i] = src[i];
  }
  // ---- stage weights / biases ----
  {
    float4* dw0 = reinterpret_cast<float4*>(&s.w0[0][0][0]);
    float4* dw1 = reinterpret_cast<float4*>(&s.w1[0][0][0]);
    float4* ddc = reinterpret_cast<float4*>(&s.dec[0][0][0]);
    const float4* sw0 = reinterpret_cast<const float4*>(g_w0);
    const float4* sw1 = reinterpret_cast<const float4*>(g_w1);
    const float4* sdc = reinterpret_cast<const float4*>(g_decw);
    for (int i = tid; i < NLAYERS * DD * DD / 4; i += NTHREADS) {
      dw0[i] = sw0[i]; dw1[i] = sw1[i]; ddc[i] = sdc[i];
    }
    float4* df1 = reinterpret_cast<float4*>(&s.fc1[0][0]);
    float4* df2 = reinterpret_cast<float4*>(&s.fc2[0][0]);
    const float4* sf1 = reinterpret_cast<const float4*>(g_fc1w);
    const float4* sf2 = reinterpret_cast<const float4*>(g_fc2w);
    for (int i = tid; i < DD * DD / 4; i += NTHREADS) { df1[i] = sf1[i]; df2[i] = sf2[i]; }
  }
  for (int i = tid; i < NLAYERS * DD; i += NTHREADS) {
    (&s.b0[0][0])[i]   = g_b0[i];
    (&s.b1[0][0])[i]   = g_b1[i];
    (&s.decb[0][0])[i] = g_decb[i];
  }
  if (tid < DD) { s.fc1b[tid] = g_fc1b[tid]; s.fc2b[tid] = g_fc2b[tid]; }
  for (int i = tid; i < NN * DD; i += NTHREADS) (&s.wi[0][0])[i] = g_wi[i];
  if (tid < NLAYERS) s.epsp[tid] = g_eps[tid];
  for (int i = tid; i < NLAYERS * NN; i += NTHREADS) {
    float a = g_big[i] * rsqrtf(g_biv[i] + BN_EPS);
    (&s.bnia[0][0])[i] = a;
    (&s.bnib[0][0])[i] = g_bib[i] - g_bim[i] * a;
    float ao = g_bog[i] * rsqrtf(g_bov[i] + BN_EPS);
    (&s.bnoa[0][0])[i] = ao;
    (&s.bnob[0][0])[i] = g_bob[i] - g_bom[i] * ao;
  }
  __syncthreads();

  const int grp = tid >> 4;        // 8 groups, each owns TWO elements
  const int n = tid & 15;          // node index; lanes 13..15 idle
  const int e0 = grp * 2, e1 = grp * 2 + 1;
  const bool act = (n < NN);
  const unsigned mask = (tid & 16) ? 0xFFFF0000u : 0x0000FFFFu;
  const int b0g = b0blk + e0, b1g = b0blk + e1;

  u64 xa[8], xb[8];
  // ---- initial embedding for both elements ----
  if (act) {
    #pragma unroll
    for (int j = 0; j < 8; j++) { xa[j] = 0ull; xb[j] = 0ull; }
    #pragma unroll
    for (int m = 0; m < NN; m++) {
      float sa = s.adj[e0][0][n][m] + s.adj[e0][1][n][m]
               + s.adj[e0][2][n][m] + s.adj[e0][3][n][m];
      float sb = s.adj[e1][0][n][m] + s.adj[e1][1][n][m]
               + s.adj[e1][2][n][m] + s.adj[e1][3][n][m];
      u64 ba = bc2(sa), bb = bc2(sb);
      const ulonglong2* wm = reinterpret_cast<const ulonglong2*>(s.wi[m]);
      ulonglong2 wa = wm[0], wbq = wm[1], wc = wm[2], wd = wm[3];
      xa[0]=fma2(ba,wa.x,xa[0]); xa[1]=fma2(ba,wa.y,xa[1]);
      xa[2]=fma2(ba,wbq.x,xa[2]); xa[3]=fma2(ba,wbq.y,xa[3]);
      xa[4]=fma2(ba,wc.x,xa[4]); xa[5]=fma2(ba,wc.y,xa[5]);
      xa[6]=fma2(ba,wd.x,xa[6]); xa[7]=fma2(ba,wd.y,xa[7]);
      xb[0]=fma2(bb,wa.x,xb[0]); xb[1]=fma2(bb,wa.y,xb[1]);
      xb[2]=fma2(bb,wbq.x,xb[2]); xb[3]=fma2(bb,wbq.y,xb[3]);
      xb[4]=fma2(bb,wc.x,xb[4]); xb[5]=fma2(bb,wc.y,xb[5]);
      xb[6]=fma2(bb,wd.x,xb[6]); xb[7]=fma2(bb,wd.y,xb[7]);
    }
    ulonglong2* xo0 = reinterpret_cast<ulonglong2*>(s.x[e0][n]);
    ulonglong2* xo1 = reinterpret_cast<ulonglong2*>(s.x[e1][n]);
    #pragma unroll
    for (int q = 0; q < 4; q++) {
      xo0[q] = make_ulonglong2(xa[2*q], xa[2*q+1]);
      xo1[q] = make_ulonglong2(xb[2*q], xb[2*q+1]);
    }
  }
  __syncwarp(mask);

  // ---- GIN layers ----
  #pragma unroll 1
  for (int l = 0; l < NLAYERS; l++) {
    if (act) {
      u64 na[8], nb[8];
      #pragma unroll
      for (int j = 0; j < 8; j++) { na[j] = 0ull; nb[j] = 0ull; }
      #pragma unroll
      for (int m = 0; m < NN; m++) {
        u64 a0 = bc2(s.adj[e0][0][n][m]), a1 = bc2(s.adj[e0][1][n][m]);
        u64 a2 = bc2(s.adj[e0][2][n][m]), a3 = bc2(s.adj[e0][3][n][m]);
        const ulonglong2* xm0 = reinterpret_cast<const ulonglong2*>(s.x[e0][m]);
        ulonglong2 v0 = xm0[0], v1 = xm0[1], v2 = xm0[2], v3 = xm0[3];
        na[0]=fma2(a0,v0.x,na[0]); na[1]=fma2(a0,v0.y,na[1]);
        na[2]=fma2(a1,v1.x,na[2]); na[3]=fma2(a1,v1.y,na[3]);
        na[4]=fma2(a2,v2.x,na[4]); na[5]=fma2(a2,v2.y,na[5]);
        na[6]=fma2(a3,v3.x,na[6]); na[7]=fma2(a3,v3.y,na[7]);
        u64 c0 = bc2(s.adj[e1][0][n][m]), c1 = bc2(s.adj[e1][1][n][m]);
        u64 c2 = bc2(s.adj[e1][2][n][m]), c3 = bc2(s.adj[e1][3][n][m]);
        const ulonglong2* xm1 = reinterpret_cast<const ulonglong2*>(s.x[e1][m]);
        ulonglong2 u0 = xm1[0], u1 = xm1[1], u2 = xm1[2], u3 = xm1[3];
        nb[0]=fma2(c0,u0.x,nb[0]); nb[1]=fma2(c0,u0.y,nb[1]);
        nb[2]=fma2(c1,u1.x,nb[2]); nb[3]=fma2(c1,u1.y,nb[3]);
        nb[4]=fma2(c2,u2.x,nb[4]); nb[5]=fma2(c2,u2.y,nb[5]);
        nb[6]=fma2(c3,u3.x,nb[6]); nb[7]=fma2(c3,u3.y,nb[7]);
      }
      u64 ep = bc2(1.f + s.epsp[l]);
      #pragma unroll
      for (int j = 0; j < 8; j++) {
        na[j] = fma2(ep, xa[j], na[j]);
        nb[j] = fma2(ep, xb[j], nb[j]);
      }
      const float ai = s.bnia[l][n], bi = s.bnib[l][n];
      float ha[DD], hb[DD];
      #pragma unroll
      for (int o = 0; o < DD; o++) {
        float da, db;
        dot16x2(na, nb, s.w0[l][o], da, db);
        float bias = s.b0[l][o];
        ha[o] = leaky((da + bias) * ai + bi);
        hb[o] = leaky((db + bias) * ai + bi);
      }
      u64 h2a[8], h2b[8];
      #pragma unroll
      for (int j = 0; j < 8; j++) {
        h2a[j] = pk2(ha[2*j], ha[2*j+1]);
        h2b[j] = pk2(hb[2*j], hb[2*j+1]);
      }
      const float ao = s.bnoa[l][n], bo = s.bnob[l][n];
      float sxa[DD], sxb[DD];
      #pragma unroll
      for (int o = 0; o < DD; o++) {
        float da, db;
        dot16x2(h2a, h2b, s.w1[l][o], da, db);
        float bias = s.b1[l][o];
        sxa[o] = leaky((da + bias) * ao + bo);
        sxb[o] = leaky((db + bias) * ao + bo);
      }
      #pragma unroll
      for (int j = 0; j < 8; j++) {
        xa[j] = pk2(sxa[2*j], sxa[2*j+1]);
        xb[j] = pk2(sxb[2*j], sxb[2*j+1]);
      }
    }
    __syncwarp(mask);
    if (act) {
      ulonglong2* xo0 = reinterpret_cast<ulonglong2*>(s.x[e0][n]);
      ulonglong2* xo1 = reinterpret_cast<ulonglong2*>(s.x[e1][n]);
      #pragma unroll
      for (int q = 0; q < 4; q++) {
        xo0[q] = make_ulonglong2(xa[2*q], xa[2*q+1]);
        xo1[q] = make_ulonglong2(xb[2*q], xb[2*q+1]);
      }
    }
    __syncwarp(mask);
  }

  // ---- mu / logvar heads ----
  u64 mua[8], mub[8];
  if (act) {
    float ma[DD], mb[DD], la[DD], lb[DD];
    #pragma unroll
    for (int o = 0; o < DD; o++) {
      float da, db;
      dot16x2(xa, xb, s.fc1[o], da, db);
      ma[o] = da + s.fc1b[o]; mb[o] = db + s.fc1b[o];
      dot16x2(xa, xb, s.fc2[o], da, db);
      la[o] = da + s.fc2b[o]; lb[o] = db + s.fc2b[o];
    }
    #pragma unroll
    for (int j = 0; j < 8; j++) {
      mua[j] = pk2(ma[2*j], ma[2*j+1]);
      mub[j] = pk2(mb[2*j], mb[2*j+1]);
    }
    if (e0 < nelem) {
      size_t base = ((size_t)b0g * NN + n) * DD;
      float4* mo = reinterpret_cast<float4*>(o_mu + base);
      float4* lo = reinterpret_cast<float4*>(o_lv + base);
      #pragma unroll
      for (int q = 0; q < 4; q++) {
        mo[q] = make_float4(ma[4*q], ma[4*q+1], ma[4*q+2], ma[4*q+3]);
        lo[q] = make_float4(la[4*q], la[4*q+1], la[4*q+2], la[4*q+3]);
      }
    }
    if (e1 < nelem) {
      size_t base = ((size_t)b1g * NN + n) * DD;
      float4* mo = reinterpret_cast<float4*>(o_mu + base);
      float4* lo = reinterpret_cast<float4*>(o_lv + base);
      #pragma unroll
      for (int q = 0; q < 4; q++) {
        mo[q] = make_float4(mb[4*q], mb[4*q+1], mb[4*q+2], mb[4*q+3]);
        lo[q] = make_float4(lb[4*q], lb[4*q+1], lb[4*q+2], lb[4*q+3]);
      }
    }
  }

  // ---- decoder: recon[k] = relu(T T^T) is SYMMETRIC. Lane n computes pairs
  //      (n, (n+j)%13) for j=0..6 — each unordered pair exactly once (13 odd).
  //      Both mirror entries written UNCONDITIONALLY (j=0 rewrites the
  //      diagonal with the same value — no branch). ----
  float* recon0 = &s.adj[e0][0][0][0];
  float* recon1 = &s.adj[e1][0][0][0];
  #pragma unroll 1
  for (int k = 0; k < NCH; k++) {
    u64 ta[8], tb[8];
    if (act) {
      float va[DD], vb[DD];
      #pragma unroll
      for (int d = 0; d < DD; d++) {
        float da, db;
        dot16x2(mua, mub, s.dec[k][d], da, db);
        float bias = s.decb[k][d];
        va[d] = da + bias; vb[d] = db + bias;
      }
      #pragma unroll
      for (int j = 0; j < 8; j++) {
        ta[j] = pk2(va[2*j], va[2*j+1]);
        tb[j] = pk2(vb[2*j], vb[2*j+1]);
      }
    }
    __syncwarp(mask);
    if (act) {
      ulonglong2* xo0 = reinterpret_cast<ulonglong2*>(s.x[e0][n]);
      ulonglong2* xo1 = reinterpret_cast<ulonglong2*>(s.x[e1][n]);
      #pragma unroll
      for (int q = 0; q < 4; q++) {
        xo0[q] = make_ulonglong2(ta[2*q], ta[2*q+1]);
        xo1[q] = make_ulonglong2(tb[2*q], tb[2*q+1]);
      }
    }
    __syncwarp(mask);
    if (act) {
      float* rp0 = recon0 + k * (NN * NN);
      float* rp1 = recon1 + k * (NN * NN);
      #pragma unroll
      for (int j = 0; j < 7; j++) {
        int m = n + j; if (m >= NN) m -= NN;
        const ulonglong2* tm0 = reinterpret_cast<const ulonglong2*>(s.x[e0][m]);
        ulonglong2 v0 = tm0[0], v1 = tm0[1], v2 = tm0[2], v3 = tm0[3];
        u64 p = mul2(ta[0], v0.x); p = fma2(ta[1], v0.y, p);
        p = fma2(ta[2], v1.x, p);  p = fma2(ta[3], v1.y, p);
        u64 q = mul2(ta[4], v2.x); q = fma2(ta[5], v2.y, q);
        q = fma2(ta[6], v3.x, q);  q = fma2(ta[7], v3.y, q);
        float c0v = fmaxf(hsum2(add2(p, q)), 0.f);
        rp0[n * NN + m] = c0v;
        rp0[m * NN + n] = c0v;
        const ulonglong2* tm1 = reinterpret_cast<const ulonglong2*>(s.x[e1][m]);
        ulonglong2 u0 = tm1[0], u1 = tm1[1], u2 = tm1[2], u3 = tm1[3];
        u64 pb = mul2(tb[0], u0.x); pb = fma2(tb[1], u0.y, pb);
        pb = fma2(tb[2], u1.x, pb); pb = fma2(tb[3], u1.y, pb);
        u64 qb = mul2(tb[4], u2.x); qb = fma2(tb[5], u2.y, qb);
        qb = fma2(tb[6], u3.x, qb); qb = fma2(tb[7], u3.y, qb);
        float c1v = fmaxf(hsum2(add2(pb, qb)), 0.f);
        rp1[n * NN + m] = c1v;
        rp1[m * NN + n] = c1v;
      }
    }
  }

  // ---- coalesced recon store for the whole block ----
  __syncthreads();
  {
    const float4* src = reinterpret_cast<const float4*>(&s.adj[0][0][0][0]);
    float4* dst = reinterpret_cast<float4*>(o_recon + (size_t)b0blk * ADJF);
    const int cnt = nelem * ADJF / 4;
    for (int i = tid; i < cnt; i += NTHREADS) dst[i] = src[i];
  }
}

extern "C" void kernel_launch(void* const* d_in, const int* in_sizes, int n_in,
                              void* d_out, int out_size) {
  const float* g_adj  = (const float*)d_in[0];
  const float* g_wi   = (const float*)d_in[1];
  const float* g_eps  = (const float*)d_in[2];
  const float* g_w0   = (const float*)d_in[3];
  const float* g_b0   = (const float*)d_in[4];
  const float* g_w1   = (const float*)d_in[5];
  const float* g_b1   = (const float*)d_in[6];
  const float* g_big  = (const float*)d_in[7];
  const float* g_bib  = (const float*)d_in[8];
  const float* g_bim  = (const float*)d_in[9];
  const float* g_biv  = (const float*)d_in[10];
  const float* g_bog  = (const float*)d_in[11];
  const float* g_bob  = (const float*)d_in[12];
  const float* g_bom  = (const float*)d_in[13];
  const float* g_bov  = (const float*)d_in[14];
  const float* g_fc1w = (const float*)d_in[15];
  const float* g_fc1b = (const float*)d_in[16];
  const float* g_fc2w = (const float*)d_in[17];
  const float* g_fc2b = (const float*)d_in[18];
  const float* g_decw = (const float*)d_in[19];
  const float* g_decb = (const float*)d_in[20];

  const int Btot = in_sizes[0] / ADJF;
  float* out = (float*)d_out;
  float* o_recon = out;
  float* o_mu = out + (size_t)Btot * ADJF;
  float* o_lv = o_mu + (size_t)Btot * NN * DD;

  cudaFuncSetAttribute((const void*)vae_kernel,
                       cudaFuncAttributeMaxDynamicSharedMemorySize,
                       (int)sizeof(Smem));
  int grid = (Btot + EPB - 1) / EPB;
  vae_kernel<<<grid, NTHREADS, sizeof(Smem)>>>(
      g_adj, g_wi, g_eps, g_w0, g_b0, g_w1, g_b1,
      g_big, g_bib, g_bim, g_biv, g_bog, g_bob, g_bom, g_bov,
      g_fc1w, g_fc1b, g_fc2w, g_fc2b, g_decw, g_decb,
      o_recon, o_mu, o_lv, Btot);
}